// round 10
// baseline (speedup 1.0000x reference)
#include <cuda_runtime.h>
#include <math.h>

#define HS 1080
#define WS 1920
#define OUTW 3840
#define MAXN 256
#define MAXM 256
#define MAXK (2*MAXN + MAXM)
#define SUBS 8
#define DETS_PER_PASS 32
#define TILES_X 30
#define TILES_Y 68

// Rect table scratch (allocation-free: __device__ globals)
__device__ int4  g_rbox[MAXK];   // subsampled int boxes (x1,y1,x2,y2)
__device__ float g_rval[MAXK];   // paint value (<=0 -> culled)
__device__ volatile int g_ready; // producer->consumer flag (static-init 0)

__global__ void __launch_bounds__(256) fused_kernel(
    float* __restrict__ out,
    const float4* __restrict__ boxes, const float* __restrict__ scores,
    const float* __restrict__ flags,
    const float4* __restrict__ boxes_prev, const float* __restrict__ scores_prev,
    const float* __restrict__ flags_prev,
    const int* __restrict__ ids, const int* __restrict__ ids_prev,
    int N, int M)
{
    int t = threadIdx.x;

    if (blockIdx.x == 0) {
        // ───────────────────────── producer: setup ─────────────────────────
        __shared__ float4 s_pb[MAXM];
        __shared__ float  s_parea[MAXM], s_ps[MAXM], s_pf[MAXM];
        __shared__ int    s_pid[MAXM];
        __shared__ int    s_matched[MAXM];
        __shared__ float  p_best[256], p_ioum[256];
        __shared__ int    p_bidx[256], p_midx[256];

        if (t == 0) g_ready = 0;   // benign race: stale readers see identical table

        for (int j = t; j < M; j += blockDim.x) {
            float4 b = boxes_prev[j];
            float x1 = floorf(b.x * 0.5f), y1 = floorf(b.y * 0.5f);
            float x2 = floorf(b.z * 0.5f), y2 = floorf(b.w * 0.5f);
            s_pb[j] = make_float4(x1, y1, x2, y2);
            s_parea[j] = (x2 - x1) * (y2 - y1);
            s_ps[j] = scores_prev[j];
            s_pf[j] = flags_prev[j];
            s_pid[j] = ids_prev[j];
            s_matched[j] = 0;
        }
        __syncthreads();

        int sub = t & 7;

        for (int det0 = 0; det0 < N; det0 += DETS_PER_PASS) {
            int det = det0 + (t >> 3);   // 8 threads per det

            float bx1 = 0.f, by1 = 0.f, bx2 = 0.f, by2 = 0.f;

            if (det < N) {
                float4 b = boxes[det];
                bx1 = floorf(b.x * 0.5f); by1 = floorf(b.y * 0.5f);
                bx2 = floorf(b.z * 0.5f); by2 = floorf(b.w * 0.5f);
                float area = (bx2 - bx1) * (by2 - by1);
                int myid = ids[det];

                int chunk = (M + SUBS - 1) / SUBS;
                int j0 = sub * chunk;
                int j1 = min(M, j0 + chunk);

                float best = -3.0f, ioum = 0.0f, iou0 = 0.0f;
                int bidx = 0, midx = -1;
                for (int j = j0; j < j1; j++) {
                    float4 p = s_pb[j];
                    float ix1 = fmaxf(bx1, p.x), iy1 = fmaxf(by1, p.y);
                    float ix2 = fminf(bx2, p.z), iy2 = fminf(by2, p.w);
                    float inter = fmaxf(ix2 - ix1, 0.0f) * fmaxf(iy2 - iy1, 0.0f);
                    float iou = inter / (area + s_parea[j] - inter);  // exact IEEE div
                    bool ism = (s_pid[j] == myid);
                    if (ism) { midx = j; ioum = iou; }
                    float v = ism ? -1.0f : iou;
                    if (v > best) { best = v; bidx = j; }  // strict >: first argmax
                    if (j == 0) iou0 = iou;                // only sub 0 hits j==0
                }
                // reference: no id match -> midx=0, iou_m = iou[i][0]
                if (midx < 0) ioum = iou0;

                p_best[t] = best; p_bidx[t] = bidx;
                p_ioum[t] = ioum; p_midx[t] = midx;
            }
            __syncthreads();

            if (det < N && sub == 0) {
                float best = -3.0f, ioum = p_ioum[t];
                int bidx = 0, midx = 0;
                bool hasm = false;
                #pragma unroll
                for (int s = 0; s < SUBS; s++) {
                    float b = p_best[t + s];
                    if (b > best) { best = b; bidx = p_bidx[t + s]; }  // chunks ascend
                    if (!hasm && p_midx[t + s] >= 0) {
                        hasm = true; midx = p_midx[t + s]; ioum = p_ioum[t + s];
                    }
                }

                float fl = flags[det];
                float sc = scores[det];
                bool  flag1    = (fl == 1.0f);
                bool  has_best = (best > 0.0f);
                float best_iou = fmaxf(best, 0.0f);
                float ig1 = 1.0f - best_iou;
                float ig0 = 1.0f - ioum;

                // rect[det]: current box
                float val_cur = flag1 ? (ig1 * sc) : (ig0 * sc * (1.0f - fl));
                g_rbox[det] = make_int4((int)bx1, (int)by1, (int)bx2, (int)by2);
                g_rval[det] = val_cur;

                // rect[N+det]: associated prev box
                float sp1 = s_ps[bidx], fp1 = s_pf[bidx];
                float v1 = ig1 * ((fp1 == 1.0f) ? sp1 : sp1 * (1.0f - fp1));
                float sp0 = s_ps[midx], fp0 = s_pf[midx];
                float v0 = ig0 * ((fp0 == 1.0f) ? sp0 : sp0 * (1.0f - fl)); // (1-cur flag)
                int   pj   = flag1 ? bidx : midx;
                float pv   = flag1 ? v1 : v0;
                bool  pact = flag1 ? has_best : hasm;
                float4 pb = s_pb[pj];
                g_rbox[N + det] = make_int4((int)pb.x, (int)pb.y, (int)pb.z, (int)pb.w);
                g_rval[N + det] = pact ? pv : 0.0f;
                if (pact) s_matched[pj] = 1;   // non-atomic: all writers store 1
            }
            __syncthreads();
        }

        // rect[2N+j]: leftover (unmatched) prev dets, masked in-shared
        for (int j = t; j < M; j += blockDim.x) {
            float spv = s_ps[j], fpv = s_pf[j];
            float vu = (fpv == 1.0f) ? spv : spv * (1.0f - fpv);
            float4 pb = s_pb[j];
            g_rbox[2 * N + j] = make_int4((int)pb.x, (int)pb.y, (int)pb.z, (int)pb.w);
            g_rval[2 * N + j] = s_matched[j] ? 0.0f : vu;
        }

        __threadfence();
        __syncthreads();
        if (t == 0) atomicExch((int*)&g_ready, 1);
        return;
    }

    // ───────────────────────── consumers: paint ─────────────────────────
    __shared__ int4  c_box[MAXK];
    __shared__ float c_val[MAXK];
    __shared__ int   scount;

    int bid = blockIdx.x - 1;
    int tx0 = (bid % TILES_X) * 64;
    int ty0 = (bid / TILES_X) * 16;
    int sx = tx0 + ((t & 31) << 1);
    int sy = ty0 + ((t >> 5) << 1);
    int K = 2 * N + M;

    if (t == 0) {
        scount = 0;
        while (!g_ready) __nanosleep(64);
    }
    __syncthreads();
    __threadfence();   // acquire: order table reads after flag

    // Cull rects into shared compact list
    for (int r = t; r < K; r += blockDim.x) {
        float v = g_rval[r];
        int4 b = g_rbox[r];
        if (v > 0.0f && b.x < tx0 + 64 && b.z > tx0 && b.y < ty0 + 16 && b.w > ty0) {
            int idx = atomicAdd(&scount, 1);
            c_box[idx] = b;
            c_val[idx] = v;
        }
    }
    __syncthreads();

    float v00 = 0.0f, v01 = 0.0f, v10 = 0.0f, v11 = 0.0f;
    int n = scount;
    for (int r = 0; r < n; r++) {
        int4 b = c_box[r];
        float v = c_val[r];
        bool inx0 = (sx     >= b.x) & (sx     < b.z);
        bool inx1 = (sx + 1 >= b.x) & (sx + 1 < b.z);
        bool iny0 = (sy     >= b.y) & (sy     < b.w);
        bool iny1 = (sy + 1 >= b.y) & (sy + 1 < b.w);
        if (inx0 & iny0) v00 = fmaxf(v00, v);
        if (inx1 & iny0) v01 = fmaxf(v01, v);
        if (inx0 & iny1) v10 = fmaxf(v10, v);
        if (inx1 & iny1) v11 = fmaxf(v11, v);
    }

    if (sy < HS) {  // last tile row is partial in y (1080 = 67*16 + 8)
        int gx = sx << 1;
        int gy = sy << 1;
        float4 a = make_float4(v00, v00, v01, v01);
        float4 b = make_float4(v10, v10, v11, v11);
        float4* p0 = (float4*)(out + (size_t)(gy    ) * OUTW + gx);
        float4* p1 = (float4*)(out + (size_t)(gy + 1) * OUTW + gx);
        float4* p2 = (float4*)(out + (size_t)(gy + 2) * OUTW + gx);
        float4* p3 = (float4*)(out + (size_t)(gy + 3) * OUTW + gx);
        *p0 = a; *p1 = a;
        *p2 = b; *p3 = b;
    }
}

extern "C" void kernel_launch(void* const* d_in, const int* in_sizes, int n_in,
                              void* d_out, int out_size)
{
    // metadata order: inputs, boxes, scores, flags, boxes_prev, scores_prev,
    //                 flags_prev, ids, ids_prev
    const float4* boxes      = (const float4*)d_in[1];
    const float*  scores     = (const float*)d_in[2];
    const float*  flags      = (const float*)d_in[3];
    const float4* boxes_prev = (const float4*)d_in[4];
    const float*  scores_prev= (const float*)d_in[5];
    const float*  flags_prev = (const float*)d_in[6];
    const int*    ids        = (const int*)d_in[7];
    const int*    ids_prev   = (const int*)d_in[8];

    int N = in_sizes[2];   // scores element count
    int M = in_sizes[5];   // scores_prev element count

    fused_kernel<<<1 + TILES_X * TILES_Y, 256>>>(
        (float*)d_out, boxes, scores, flags, boxes_prev, scores_prev,
        flags_prev, ids, ids_prev, N, M);
}

// round 11
// speedup vs baseline: 2.3125x; 2.3125x over previous
#include <cuda_runtime.h>
#include <math.h>

#define HS 1080
#define WS 1920
#define OUTW 3840
#define MAXN 256
#define MAXM 256
#define MAXK (2*MAXN + MAXM)
#define TILES_X 30
#define TILES_Y 68

// Rect table scratch (allocation-free: __device__ globals)
__device__ int4  g_rbox[MAXK];   // subsampled int boxes (x1,y1,x2,y2)
__device__ float g_rval[MAXK];   // paint value (<=0 -> culled)
__device__ int   g_pj[MAXN];     // matched prev index per current det, -1 if none

// Warp-per-det setup. Blocks [0, detBlocks): 8 warps = 8 dets each.
// Block detBlocks: writes the M leftover-prev rects (unmasked; paint masks).
__global__ void __launch_bounds__(256) setup_kernel(
    const float4* __restrict__ boxes, const float* __restrict__ scores,
    const float* __restrict__ flags,
    const float4* __restrict__ boxes_prev, const float* __restrict__ scores_prev,
    const float* __restrict__ flags_prev,
    const int* __restrict__ ids, const int* __restrict__ ids_prev,
    int N, int M, int detBlocks)
{
    int t = threadIdx.x;

    if (blockIdx.x == detBlocks) {
        // leftover (unmatched) prev rects — value independent of matching
        for (int j = t; j < M; j += blockDim.x) {
            float4 b = boxes_prev[j];
            float x1 = floorf(b.x * 0.5f), y1 = floorf(b.y * 0.5f);
            float x2 = floorf(b.z * 0.5f), y2 = floorf(b.w * 0.5f);
            float spv = scores_prev[j], fpv = flags_prev[j];
            float vu = (fpv == 1.0f) ? spv : spv * (1.0f - fpv);
            g_rbox[2 * N + j] = make_int4((int)x1, (int)y1, (int)x2, (int)y2);
            g_rval[2 * N + j] = vu;
        }
        return;
    }

    int det  = blockIdx.x * 8 + (t >> 5);
    int lane = t & 31;
    if (det >= N) return;

    float4 b = boxes[det];
    float bx1 = floorf(b.x * 0.5f), by1 = floorf(b.y * 0.5f);
    float bx2 = floorf(b.z * 0.5f), by2 = floorf(b.w * 0.5f);
    float area = (bx2 - bx1) * (by2 - by1);
    int myid = ids[det];

    int C = (M + 31) >> 5;          // js per lane (contiguous chunk, ascending)
    int j0 = lane * C;
    int j1 = min(M, j0 + C);

    float best = -3.0f, ioum = 0.0f, iou0 = 0.0f;
    int bidx = MAXK, midx = -1;
    for (int j = j0; j < j1; j++) {
        float4 p = boxes_prev[j];
        float px1 = floorf(p.x * 0.5f), py1 = floorf(p.y * 0.5f);
        float px2 = floorf(p.z * 0.5f), py2 = floorf(p.w * 0.5f);
        float parea = (px2 - px1) * (py2 - py1);
        float ix1 = fmaxf(bx1, px1), iy1 = fmaxf(by1, py1);
        float ix2 = fminf(bx2, px2), iy2 = fminf(by2, py2);
        float inter = fmaxf(ix2 - ix1, 0.0f) * fmaxf(iy2 - iy1, 0.0f);
        float iou = inter / (area + parea - inter);   // exact IEEE div, matches jnp
        bool ism = (ids_prev[j] == myid);
        if (ism) { midx = j; ioum = iou; }
        float v = ism ? -1.0f : iou;
        if (v > best) { best = v; bidx = j; }         // in-lane ascending: first argmax
        if (j == 0) iou0 = iou;                       // only lane 0 hits j==0
    }

    // cross-lane reduce to lane 0: max with smaller-index tie-break (first argmax)
    #pragma unroll
    for (int off = 16; off > 0; off >>= 1) {
        float ob  = __shfl_down_sync(0xffffffffu, best, off);
        int   obi = __shfl_down_sync(0xffffffffu, bidx, off);
        float om  = __shfl_down_sync(0xffffffffu, ioum, off);
        int   omi = __shfl_down_sync(0xffffffffu, midx, off);
        if (ob > best || (ob == best && obi < bidx)) { best = ob; bidx = obi; }
        if (midx < 0 && omi >= 0) { midx = omi; ioum = om; }   // ids unique
    }

    if (lane == 0) {
        bool hasm = (midx >= 0);
        if (!hasm) { midx = 0; ioum = iou0; }   // reference: argmax of all-false -> 0

        float fl = flags[det];
        float sc = scores[det];
        bool  flag1    = (fl == 1.0f);
        bool  has_best = (best > 0.0f);
        float best_iou = fmaxf(best, 0.0f);
        float ig1 = 1.0f - best_iou;
        float ig0 = 1.0f - ioum;

        // rect[det]: current box
        float val_cur = flag1 ? (ig1 * sc) : (ig0 * sc * (1.0f - fl));
        g_rbox[det] = make_int4((int)bx1, (int)by1, (int)bx2, (int)by2);
        g_rval[det] = val_cur;

        // rect[N+det]: associated prev box
        float sp1 = scores_prev[bidx], fp1 = flags_prev[bidx];
        float v1 = ig1 * ((fp1 == 1.0f) ? sp1 : sp1 * (1.0f - fp1));
        float sp0 = scores_prev[midx], fp0 = flags_prev[midx];
        float v0 = ig0 * ((fp0 == 1.0f) ? sp0 : sp0 * (1.0f - fl)); // (1 - cur flag)
        int   pj   = flag1 ? bidx : midx;
        float pv   = flag1 ? v1 : v0;
        bool  pact = flag1 ? has_best : hasm;
        float4 p = boxes_prev[pj];
        g_rbox[N + det] = make_int4((int)floorf(p.x * 0.5f), (int)floorf(p.y * 0.5f),
                                    (int)floorf(p.z * 0.5f), (int)floorf(p.w * 0.5f));
        g_rval[N + det] = pact ? pv : 0.0f;
        g_pj[det] = pact ? pj : -1;
    }
}

// Tile: 64 (x) x 16 (y) sub-pixels per block, 256 threads, each owns a 2x2
// sub-pixel patch -> writes a 4x4 full-res patch via 4 float4 stores.
__global__ void __launch_bounds__(256) paint_kernel(float* __restrict__ out, int N, int M)
{
    __shared__ int4  c_box[MAXK];
    __shared__ float c_val[MAXK];
    __shared__ unsigned int mbits[MAXM / 32];
    __shared__ int   scount;

    int t = threadIdx.x;
    if (t < MAXM / 32) mbits[t] = 0u;
    if (t == 0) scount = 0;
    __syncthreads();

    // matched-prev bitmask from per-det matched index
    for (int i = t; i < N; i += blockDim.x) {
        int pj = g_pj[i];
        if (pj >= 0) atomicOr(&mbits[pj >> 5], 1u << (pj & 31));
    }
    __syncthreads();

    int tx0 = blockIdx.x * 64;
    int ty0 = blockIdx.y * 16;
    int K = 2 * N + M;

    // Cull rects into shared compact list
    for (int r = t; r < K; r += blockDim.x) {
        float v = g_rval[r];
        int4 b = g_rbox[r];
        bool masked = (r >= 2 * N) &&
                      ((mbits[(r - 2 * N) >> 5] >> ((r - 2 * N) & 31)) & 1u);
        if (!masked && v > 0.0f &&
            b.x < tx0 + 64 && b.z > tx0 && b.y < ty0 + 16 && b.w > ty0) {
            int idx = atomicAdd(&scount, 1);
            c_box[idx] = b;
            c_val[idx] = v;
        }
    }
    __syncthreads();

    int sx = tx0 + ((t & 31) << 1);
    int sy = ty0 + ((t >> 5) << 1);

    float v00 = 0.0f, v01 = 0.0f, v10 = 0.0f, v11 = 0.0f;
    int n = scount;
    for (int r = 0; r < n; r++) {
        int4 b = c_box[r];
        float v = c_val[r];
        bool inx0 = (sx     >= b.x) & (sx     < b.z);
        bool inx1 = (sx + 1 >= b.x) & (sx + 1 < b.z);
        bool iny0 = (sy     >= b.y) & (sy     < b.w);
        bool iny1 = (sy + 1 >= b.y) & (sy + 1 < b.w);
        if (inx0 & iny0) v00 = fmaxf(v00, v);
        if (inx1 & iny0) v01 = fmaxf(v01, v);
        if (inx0 & iny1) v10 = fmaxf(v10, v);
        if (inx1 & iny1) v11 = fmaxf(v11, v);
    }

    if (sy < HS) {  // last block row is partial in y (1080 = 67*16 + 8)
        int gx = sx << 1;
        int gy = sy << 1;
        float4 a = make_float4(v00, v00, v01, v01);
        float4 b = make_float4(v10, v10, v11, v11);
        float4* p0 = (float4*)(out + (size_t)(gy    ) * OUTW + gx);
        float4* p1 = (float4*)(out + (size_t)(gy + 1) * OUTW + gx);
        float4* p2 = (float4*)(out + (size_t)(gy + 2) * OUTW + gx);
        float4* p3 = (float4*)(out + (size_t)(gy + 3) * OUTW + gx);
        *p0 = a; *p1 = a;
        *p2 = b; *p3 = b;
    }
}

extern "C" void kernel_launch(void* const* d_in, const int* in_sizes, int n_in,
                              void* d_out, int out_size)
{
    // metadata order: inputs, boxes, scores, flags, boxes_prev, scores_prev,
    //                 flags_prev, ids, ids_prev
    const float4* boxes      = (const float4*)d_in[1];
    const float*  scores     = (const float*)d_in[2];
    const float*  flags      = (const float*)d_in[3];
    const float4* boxes_prev = (const float4*)d_in[4];
    const float*  scores_prev= (const float*)d_in[5];
    const float*  flags_prev = (const float*)d_in[6];
    const int*    ids        = (const int*)d_in[7];
    const int*    ids_prev   = (const int*)d_in[8];

    int N = in_sizes[2];   // scores element count
    int M = in_sizes[5];   // scores_prev element count

    int detBlocks = (N + 7) / 8;   // 8 warps (dets) per block
    setup_kernel<<<detBlocks + 1, 256>>>(boxes, scores, flags, boxes_prev,
                                         scores_prev, flags_prev, ids, ids_prev,
                                         N, M, detBlocks);

    dim3 grid(TILES_X, TILES_Y);   // 30 x 68
    paint_kernel<<<grid, 256>>>((float*)d_out, N, M);
}